// round 15
// baseline (speedup 1.0000x reference)
#include <cuda_runtime.h>
#include <cuda_fp16.h>
#include <math.h>
#include <stdint.h>

#define DIM   1024
#define HMID  512
#define HLOW  256
#define ROWS  32768   // 4 * 8192

// ---------------- scratch (device globals; allocation-free) ----------------
__device__ __half g_buf1[ROWS * HMID];   // 32 MB
__device__ __half g_buf2[ROWS * HMID];   // 32 MB
__device__ float  g_mu[ROWS];
__device__ float  g_rstd[ROWS];
__device__ __half g_w1h[DIM  * HMID];
__device__ __half g_w2h[HMID * HMID];
__device__ __half g_w3h[HMID * HLOW];
__device__ __half g_w4h[HLOW * DIM];

// ---------------- helpers ----------------
__device__ __forceinline__ uint32_t h2_bits(__half2 h) {
    union { __half2 h; uint32_t u; } c;
    c.h = h;
    return c.u;
}
__device__ __forceinline__ float gelu_f(float v) {
    return 0.5f * v * (1.0f + erff(v * 0.70710678118654752440f));
}
__device__ __forceinline__ uint32_t smem_u32(const void* p) {
    uint32_t a;
    asm("{ .reg .u64 t; cvta.to.shared.u64 t, %1; cvt.u32.u64 %0, t; }" : "=r"(a) : "l"(p));
    return a;
}
__device__ __forceinline__ void cp16(uint32_t dst, const void* src) {
    asm volatile("cp.async.cg.shared.global [%0], [%1], 16;" :: "r"(dst), "l"(src));
}
__device__ __forceinline__ void cp_commit() {
    asm volatile("cp.async.commit_group;" ::: "memory");
}
template <int N>
__device__ __forceinline__ void cp_wait() {
    asm volatile("cp.async.wait_group %0;" :: "n"(N) : "memory");
}
__device__ __forceinline__ void ldsm_x4(uint32_t* r, uint32_t addr) {
    asm volatile("ldmatrix.sync.aligned.m8n8.x4.shared.b16 {%0,%1,%2,%3}, [%4];"
        : "=r"(r[0]), "=r"(r[1]), "=r"(r[2]), "=r"(r[3]) : "r"(addr));
}
__device__ __forceinline__ void ldsm_x4_t(uint32_t* r, uint32_t addr) {
    asm volatile("ldmatrix.sync.aligned.m8n8.x4.trans.shared.b16 {%0,%1,%2,%3}, [%4];"
        : "=r"(r[0]), "=r"(r[1]), "=r"(r[2]), "=r"(r[3]) : "r"(addr));
}
__device__ __forceinline__ void mma_f16(float* d, const uint32_t* a, const uint32_t* b) {
    asm volatile(
        "mma.sync.aligned.m16n8k16.row.col.f32.f16.f16.f32 "
        "{%0,%1,%2,%3}, {%4,%5,%6,%7}, {%8,%9}, {%0,%1,%2,%3};"
        : "+f"(d[0]), "+f"(d[1]), "+f"(d[2]), "+f"(d[3])
        : "r"(a[0]), "r"(a[1]), "r"(a[2]), "r"(a[3]), "r"(b[0]), "r"(b[1]));
}

// ---------------------------------------------------------------------------
// Row stats for LayerNorm (mu, rstd) — LN itself is folded into GEMM1 A-fill
// ---------------------------------------------------------------------------
__global__ void rowstats_kernel(const float* __restrict__ x) {
    const int row = blockIdx.x;
    const float4* xr = reinterpret_cast<const float4*>(x + (size_t)row * DIM);
    float4 v = xr[threadIdx.x];
    float s  = v.x + v.y + v.z + v.w;
    float sq = v.x * v.x + v.y * v.y + v.z * v.z + v.w * v.w;
    __shared__ float ss[8], ssq[8];
    #pragma unroll
    for (int o = 16; o > 0; o >>= 1) {
        s  += __shfl_down_sync(0xffffffffu, s,  o);
        sq += __shfl_down_sync(0xffffffffu, sq, o);
    }
    const int warp = threadIdx.x >> 5, lane = threadIdx.x & 31;
    if (lane == 0) { ss[warp] = s; ssq[warp] = sq; }
    __syncthreads();
    if (warp == 0) {
        s  = (lane < 8) ? ss[lane]  : 0.0f;
        sq = (lane < 8) ? ssq[lane] : 0.0f;
        #pragma unroll
        for (int o = 4; o > 0; o >>= 1) {
            s  += __shfl_down_sync(0xffffffffu, s,  o);
            sq += __shfl_down_sync(0xffffffffu, sq, o);
        }
        if (lane == 0) {
            float mu  = s * (1.0f / DIM);
            float var = sq * (1.0f / DIM) - mu * mu;
            g_mu[row]   = mu;
            g_rstd[row] = rsqrtf(var + 1e-5f);
        }
    }
}

// fp32 -> fp16: all four weight matrices in ONE launch
#define NW1 (DIM * HMID)
#define NW2 (HMID * HMID)
#define NW3 (HMID * HLOW)
#define NW4 (HLOW * DIM)
#define NWT (NW1 + NW2 + NW3 + NW4)

__global__ void to_half_all(const float* __restrict__ W1, const float* __restrict__ W2,
                            const float* __restrict__ W3, const float* __restrict__ W4) {
    const int i = (blockIdx.x * blockDim.x + threadIdx.x) * 4;
    if (i >= NWT) return;
    const float* src;
    __half* dst;
    int off;
    if (i < NW1)                   { src = W1; dst = g_w1h; off = i; }
    else if (i < NW1 + NW2)        { src = W2; dst = g_w2h; off = i - NW1; }
    else if (i < NW1 + NW2 + NW3)  { src = W3; dst = g_w3h; off = i - NW1 - NW2; }
    else                           { src = W4; dst = g_w4h; off = i - NW1 - NW2 - NW3; }
    float4 v = *reinterpret_cast<const float4*>(src + off);
    __half2 h01 = __floats2half2_rn(v.x, v.y);
    __half2 h23 = __floats2half2_rn(v.z, v.w);
    uint2 pk = make_uint2(h2_bits(h01), h2_bits(h23));
    *reinterpret_cast<uint2*>(dst + off) = pk;
}

// ---------------------------------------------------------------------------
// fp16 mma.sync GEMM: C[M,N] = epi(A[M,K] @ B[K,N] + bias)
//   CTA 64x128, BK=32, 8 warps (32x32 warp tiles), 3-stage cp.async,
//   fully unrolled K-loop, 4 CTAs/SM (32 warps).
//   LNA: A is fp32 x; LayerNorm applied in-register during A-fill.
//   EPI 0: GELU -> fp16   EPI 1: +resid -> fp32 via smem-staged coalesced RMW
// ---------------------------------------------------------------------------
static constexpr int AS_STRIDE = 40;    // halves per A smem row (64 rows): 80B
static constexpr int BS_STRIDE = 136;   // halves per B smem row (32 rows): 272B
static constexpr int A_HALVES  = 64 * AS_STRIDE;                     // 2560
static constexpr int STAGE_BYTES = (A_HALVES + 32 * BS_STRIDE) * 2;  // 13824
static constexpr int SMEM_BYTES  = 3 * STAGE_BYTES;                  // 41472
static constexpr int OUT_STRIDE = 132;  // fp32 staging stride (EPI 1)

template <int K, int N, int EPI, bool LNA>
__global__ void __launch_bounds__(256, 4)
mma_gemm(const __half* __restrict__ A, const __half* __restrict__ B,
         const float* __restrict__ bias, void* __restrict__ Cv,
         const float* __restrict__ resid,
         const float* __restrict__ Ax,        // LNA: fp32 x
         const float* __restrict__ gamma, const float* __restrict__ beta) {
    constexpr int BM = 64, BN = 128, BK = 32;
    constexpr int NT = K / BK;
    extern __shared__ __half sm[];
    const uint32_t sb = smem_u32(sm);
    const int bm = blockIdx.y * BM;
    const int bn = blockIdx.x * BN;
    const int tid  = threadIdx.x;
    const int warp = tid >> 5, lane = tid & 31;
    const int wm = warp >> 2, wn = warp & 3;     // warp tile rows wm*32, cols wn*32

    float acc[2][4][4];
    #pragma unroll
    for (int mt = 0; mt < 2; mt++)
        #pragma unroll
        for (int nt = 0; nt < 4; nt++)
            #pragma unroll
            for (int r = 0; r < 4; r++) acc[mt][nt][r] = 0.0f;

    // per-thread gmem bases
    const int a_r = tid >> 2, a_c = tid & 3;         // A: 64 rows x 4 chunks (8 halves)
    const int b_r = tid >> 4, b_c = tid & 15;        // B: 32(x2) rows x 16 chunks
    const __half* a_src0 = LNA ? nullptr : A + (size_t)(bm + a_r) * K + a_c * 8;
    const float*  ax_src0 = LNA ? Ax + (size_t)(bm + a_r) * K + a_c * 8 : nullptr;
    const __half* b_src0 = B + (size_t)b_r * N + bn + b_c * 8;
    const uint32_t a_dst_off = (uint32_t)(a_r * AS_STRIDE + a_c * 8) * 2;
    const uint32_t b_dst_off = (uint32_t)(A_HALVES + b_r * BS_STRIDE + b_c * 8) * 2;

    float mu = 0.0f, rs = 1.0f;
    if (LNA) { mu = g_mu[bm + a_r]; rs = g_rstd[bm + a_r]; }

    auto load_tile = [&](int s, int t) {
        const uint32_t base = sb + (uint32_t)(s * STAGE_BYTES);
        if (LNA) {
            const int kc = t * BK + a_c * 8;
            float4 v0 = *reinterpret_cast<const float4*>(ax_src0 + (size_t)t * BK);
            float4 v1 = *reinterpret_cast<const float4*>(ax_src0 + (size_t)t * BK + 4);
            const float4 g0  = __ldg(reinterpret_cast<const float4*>(gamma + kc));
            const float4 g1  = __ldg(reinterpret_cast<const float4*>(gamma + kc + 4));
            const float4 be0 = __ldg(reinterpret_cast<const float4*>(beta + kc));
            const float4 be1 = __ldg(reinterpret_cast<const float4*>(beta + kc + 4));
            __half2 h0 = __floats2half2_rn((v0.x - mu) * rs * g0.x + be0.x,
                                           (v0.y - mu) * rs * g0.y + be0.y);
            __half2 h1 = __floats2half2_rn((v0.z - mu) * rs * g0.z + be0.z,
                                           (v0.w - mu) * rs * g0.w + be0.w);
            __half2 h2 = __floats2half2_rn((v1.x - mu) * rs * g1.x + be1.x,
                                           (v1.y - mu) * rs * g1.y + be1.y);
            __half2 h3 = __floats2half2_rn((v1.z - mu) * rs * g1.z + be1.z,
                                           (v1.w - mu) * rs * g1.w + be1.w);
            uint4 pk = make_uint4(h2_bits(h0), h2_bits(h1), h2_bits(h2), h2_bits(h3));
            asm volatile("st.shared.v4.b32 [%0], {%1,%2,%3,%4};"
                :: "r"(base + a_dst_off), "r"(pk.x), "r"(pk.y), "r"(pk.z), "r"(pk.w)
                : "memory");
        } else {
            cp16(base + a_dst_off, a_src0 + (size_t)t * BK);
        }
        cp16(base + b_dst_off, b_src0 + (size_t)t * BK * N);
        cp16(base + b_dst_off + 16 * BS_STRIDE * 2, b_src0 + (size_t)(t * BK + 16) * N);
        cp_commit();
    };

    // hoisted ldmatrix fragment offsets (within a stage)
    const uint32_t a_frag_off = (uint32_t)((wm * 32 + (lane & 15)) * AS_STRIDE
                                           + 8 * (lane >> 4)) * 2;
    const uint32_t b_frag_off = (uint32_t)(A_HALVES * 2)
        + (uint32_t)((lane & 15) * BS_STRIDE + wn * 32 + 8 * (lane >> 4)) * 2;

    load_tile(0, 0);
    if (NT > 1) load_tile(1, 1);

    #pragma unroll
    for (int t = 0; t < NT; t++) {
        if (t + 1 < NT) cp_wait<1>(); else cp_wait<0>();
        __syncthreads();
        if (t + 2 < NT) load_tile((t + 2) % 3, t + 2);

        const uint32_t stage = sb + (uint32_t)((t % 3) * STAGE_BYTES);
        #pragma unroll
        for (int kk = 0; kk < 2; kk++) {
            uint32_t a[2][4], b[2][4];
            #pragma unroll
            for (int mt = 0; mt < 2; mt++)
                ldsm_x4(a[mt], stage + a_frag_off
                        + (uint32_t)(mt * 16 * AS_STRIDE + kk * 16) * 2);
            #pragma unroll
            for (int np = 0; np < 2; np++)
                ldsm_x4_t(b[np], stage + b_frag_off
                          + (uint32_t)(np * 16 + kk * 16 * BS_STRIDE) * 2);
            #pragma unroll
            for (int mt = 0; mt < 2; mt++)
                #pragma unroll
                for (int nt = 0; nt < 4; nt++)
                    mma_f16(acc[mt][nt], a[mt], &b[nt >> 1][(nt & 1) * 2]);
        }
    }

    // ---- epilogue ----
    const int g = lane >> 2, tg = lane & 3;
    if (EPI == 0) {
        #pragma unroll
        for (int mt = 0; mt < 2; mt++) {
            #pragma unroll
            for (int nt = 0; nt < 4; nt++) {
                const int col = bn + wn * 32 + nt * 8 + tg * 2;
                const float bx = __ldg(bias + col), by = __ldg(bias + col + 1);
                #pragma unroll
                for (int h = 0; h < 2; h++) {
                    const int row = bm + wm * 32 + mt * 16 + g + h * 8;
                    float ox = acc[mt][nt][2 * h + 0] + bx;
                    float oy = acc[mt][nt][2 * h + 1] + by;
                    __half2 hv = __floats2half2_rn(gelu_f(ox), gelu_f(oy));
                    *reinterpret_cast<__half2*>((__half*)Cv + (size_t)row * N + col) = hv;
                }
            }
        }
    } else {
        // stage the 64x128 fp32 tile in smem, then coalesced float4 RMW
        __syncthreads();                       // all mainloop smem reads done
        float* stg = reinterpret_cast<float*>(sm);
        #pragma unroll
        for (int mt = 0; mt < 2; mt++) {
            #pragma unroll
            for (int nt = 0; nt < 4; nt++) {
                const int col = wn * 32 + nt * 8 + tg * 2;
                const float bx = __ldg(bias + bn + col), by = __ldg(bias + bn + col + 1);
                #pragma unroll
                for (int h = 0; h < 2; h++) {
                    const int row = wm * 32 + mt * 16 + g + h * 8;
                    float2 o;
                    o.x = acc[mt][nt][2 * h + 0] + bx;
                    o.y = acc[mt][nt][2 * h + 1] + by;
                    *reinterpret_cast<float2*>(&stg[row * OUT_STRIDE + col]) = o;
                }
            }
        }
        __syncthreads();
        #pragma unroll
        for (int j = 0; j < 8; j++) {
            const int idx = tid + j * 256;          // 0..2047
            const int r = idx >> 5, c4 = (idx & 31) * 4;
            float4 v = *reinterpret_cast<const float4*>(&stg[r * OUT_STRIDE + c4]);
            const size_t go = (size_t)(bm + r) * N + bn + c4;
            const float4 rr = *reinterpret_cast<const float4*>(resid + go);
            v.x += rr.x; v.y += rr.y; v.z += rr.z; v.w += rr.w;
            *reinterpret_cast<float4*>((float*)Cv + go) = v;
        }
    }
}

// ---------------------------------------------------------------------------
extern "C" void kernel_launch(void* const* d_in, const int* in_sizes, int n_in,
                              void* d_out, int out_size) {
    const float* x     = (const float*)d_in[0];
    const float* gamma = (const float*)d_in[1];
    const float* beta  = (const float*)d_in[2];
    const float* W1    = (const float*)d_in[3];
    const float* b1    = (const float*)d_in[4];
    const float* W2    = (const float*)d_in[5];
    const float* b2    = (const float*)d_in[6];
    const float* W3    = (const float*)d_in[7];
    const float* b3    = (const float*)d_in[8];
    const float* W4    = (const float*)d_in[9];
    const float* b4    = (const float*)d_in[10];
    float* out = (float*)d_out;

    __half *buf1, *buf2, *w1, *w2, *w3, *w4;
    cudaGetSymbolAddress((void**)&buf1, g_buf1);
    cudaGetSymbolAddress((void**)&buf2, g_buf2);
    cudaGetSymbolAddress((void**)&w1,   g_w1h);
    cudaGetSymbolAddress((void**)&w2,   g_w2h);
    cudaGetSymbolAddress((void**)&w3,   g_w3h);
    cudaGetSymbolAddress((void**)&w4,   g_w4h);

    cudaFuncSetAttribute(mma_gemm<DIM,  HMID, 0, true>,  cudaFuncAttributeMaxDynamicSharedMemorySize, SMEM_BYTES);
    cudaFuncSetAttribute(mma_gemm<HMID, HMID, 0, false>, cudaFuncAttributeMaxDynamicSharedMemorySize, SMEM_BYTES);
    cudaFuncSetAttribute(mma_gemm<HMID, HLOW, 0, false>, cudaFuncAttributeMaxDynamicSharedMemorySize, SMEM_BYTES);
    cudaFuncSetAttribute(mma_gemm<HLOW, DIM,  1, false>, cudaFuncAttributeMaxDynamicSharedMemorySize, SMEM_BYTES);

    rowstats_kernel<<<ROWS, 256>>>(x);
    to_half_all<<<(NWT / 4 + 255) / 256, 256>>>(W1, W2, W3, W4);

    // GEMM1: LN(x)[32768,1024] @ W1 -> gelu -> buf1 (fp16), LN fused into A-fill
    mma_gemm<DIM, HMID, 0, true>
        <<<dim3(HMID / 128, ROWS / 64), 256, SMEM_BYTES>>>(nullptr, w1, b1, buf1, nullptr,
                                                           x, gamma, beta);
    // GEMM2: buf1 @ W2 -> gelu -> buf2 (fp16)
    mma_gemm<HMID, HMID, 0, false>
        <<<dim3(HMID / 128, ROWS / 64), 256, SMEM_BYTES>>>(buf1, w2, b2, buf2, nullptr,
                                                           nullptr, nullptr, nullptr);
    // GEMM3: buf2 @ W3 -> gelu -> buf1 (fp16)
    mma_gemm<HMID, HLOW, 0, false>
        <<<dim3(HLOW / 128, ROWS / 64), 256, SMEM_BYTES>>>(buf2, w3, b3, buf1, nullptr,
                                                           nullptr, nullptr, nullptr);
    // GEMM4: buf1 @ W4 + b4 + x -> out (fp32)
    mma_gemm<HLOW, DIM, 1, false>
        <<<dim3(DIM / 128, ROWS / 64), 256, SMEM_BYTES>>>(buf1, w4, b4, out, x,
                                                          nullptr, nullptr, nullptr);
}

// round 16
// speedup vs baseline: 1.8515x; 1.8515x over previous
#include <cuda_runtime.h>
#include <cuda_fp16.h>
#include <math.h>
#include <stdint.h>

#define DIM   1024
#define HMID  512
#define HLOW  256
#define ROWS  32768   // 4 * 8192

// ---------------- scratch (device globals; allocation-free) ----------------
__device__ __half g_lnh [ROWS * DIM];    // 64 MB  LN(x) in fp16
__device__ __half g_buf1[ROWS * HMID];   // 32 MB
__device__ __half g_buf2[ROWS * HMID];   // 32 MB
__device__ __half g_w1h[DIM  * HMID];
__device__ __half g_w2h[HMID * HMID];
__device__ __half g_w3h[HMID * HLOW];
__device__ __half g_w4h[HLOW * DIM];

// ---------------- helpers ----------------
__device__ __forceinline__ uint32_t h2_bits(__half2 h) {
    union { __half2 h; uint32_t u; } c;
    c.h = h;
    return c.u;
}
__device__ __forceinline__ float gelu_f(float v) {
    return 0.5f * v * (1.0f + erff(v * 0.70710678118654752440f));
}
__device__ __forceinline__ uint32_t smem_u32(const void* p) {
    uint32_t a;
    asm("{ .reg .u64 t; cvta.to.shared.u64 t, %1; cvt.u32.u64 %0, t; }" : "=r"(a) : "l"(p));
    return a;
}
__device__ __forceinline__ void cp16(uint32_t dst, const void* src) {
    asm volatile("cp.async.cg.shared.global [%0], [%1], 16;" :: "r"(dst), "l"(src));
}
__device__ __forceinline__ void cp_commit() {
    asm volatile("cp.async.commit_group;" ::: "memory");
}
template <int N>
__device__ __forceinline__ void cp_wait() {
    asm volatile("cp.async.wait_group %0;" :: "n"(N) : "memory");
}
__device__ __forceinline__ void ldsm_x4(uint32_t* r, uint32_t addr) {
    asm volatile("ldmatrix.sync.aligned.m8n8.x4.shared.b16 {%0,%1,%2,%3}, [%4];"
        : "=r"(r[0]), "=r"(r[1]), "=r"(r[2]), "=r"(r[3]) : "r"(addr));
}
__device__ __forceinline__ void ldsm_x4_t(uint32_t* r, uint32_t addr) {
    asm volatile("ldmatrix.sync.aligned.m8n8.x4.trans.shared.b16 {%0,%1,%2,%3}, [%4];"
        : "=r"(r[0]), "=r"(r[1]), "=r"(r[2]), "=r"(r[3]) : "r"(addr));
}
__device__ __forceinline__ void mma_f16(float* d, const uint32_t* a, const uint32_t* b) {
    asm volatile(
        "mma.sync.aligned.m16n8k16.row.col.f32.f16.f16.f32 "
        "{%0,%1,%2,%3}, {%4,%5,%6,%7}, {%8,%9}, {%0,%1,%2,%3};"
        : "+f"(d[0]), "+f"(d[1]), "+f"(d[2]), "+f"(d[3])
        : "r"(a[0]), "r"(a[1]), "r"(a[2]), "r"(a[3]), "r"(b[0]), "r"(b[1]));
}

// ---------------------------------------------------------------------------
// Fused prep: blocks [0, ROWS) do LayerNorm->fp16; blocks beyond convert weights.
// ---------------------------------------------------------------------------
#define NW1 (DIM * HMID)
#define NW2 (HMID * HMID)
#define NW3 (HMID * HLOW)
#define NW4 (HLOW * DIM)
#define NWT (NW1 + NW2 + NW3 + NW4)
#define WBLOCKS ((NWT / 4 + 255) / 256)   // 1152

__global__ void prep_kernel(const float* __restrict__ x, const float* __restrict__ gamma,
                            const float* __restrict__ beta, __half* __restrict__ out,
                            const float* __restrict__ W1, const float* __restrict__ W2,
                            const float* __restrict__ W3, const float* __restrict__ W4) {
    if (blockIdx.x >= ROWS) {
        const int i = ((blockIdx.x - ROWS) * blockDim.x + threadIdx.x) * 4;
        if (i >= NWT) return;
        const float* src;
        __half* dst;
        int off;
        if (i < NW1)                   { src = W1; dst = g_w1h; off = i; }
        else if (i < NW1 + NW2)        { src = W2; dst = g_w2h; off = i - NW1; }
        else if (i < NW1 + NW2 + NW3)  { src = W3; dst = g_w3h; off = i - NW1 - NW2; }
        else                           { src = W4; dst = g_w4h; off = i - NW1 - NW2 - NW3; }
        float4 v = *reinterpret_cast<const float4*>(src + off);
        __half2 h01 = __floats2half2_rn(v.x, v.y);
        __half2 h23 = __floats2half2_rn(v.z, v.w);
        uint2 pk = make_uint2(h2_bits(h01), h2_bits(h23));
        *reinterpret_cast<uint2*>(dst + off) = pk;
        return;
    }
    const int row = blockIdx.x;
    const float4* xr = reinterpret_cast<const float4*>(x + (size_t)row * DIM);
    float4 v = xr[threadIdx.x];
    float s  = v.x + v.y + v.z + v.w;
    float sq = v.x * v.x + v.y * v.y + v.z * v.z + v.w * v.w;
    __shared__ float ss[8], ssq[8];
    __shared__ float s_mu, s_rs;
    #pragma unroll
    for (int o = 16; o > 0; o >>= 1) {
        s  += __shfl_down_sync(0xffffffffu, s,  o);
        sq += __shfl_down_sync(0xffffffffu, sq, o);
    }
    const int warp = threadIdx.x >> 5, lane = threadIdx.x & 31;
    if (lane == 0) { ss[warp] = s; ssq[warp] = sq; }
    __syncthreads();
    if (warp == 0) {
        s  = (lane < 8) ? ss[lane]  : 0.0f;
        sq = (lane < 8) ? ssq[lane] : 0.0f;
        #pragma unroll
        for (int o = 4; o > 0; o >>= 1) {
            s  += __shfl_down_sync(0xffffffffu, s,  o);
            sq += __shfl_down_sync(0xffffffffu, sq, o);
        }
        if (lane == 0) {
            float mu  = s * (1.0f / DIM);
            float var = sq * (1.0f / DIM) - mu * mu;
            s_mu = mu;
            s_rs = rsqrtf(var + 1e-5f);
        }
    }
    __syncthreads();
    const float mu = s_mu, rs = s_rs;
    const int c = threadIdx.x * 4;
    const float4 g  = *reinterpret_cast<const float4*>(gamma + c);
    const float4 be = *reinterpret_cast<const float4*>(beta + c);
    __half2 h01 = __floats2half2_rn((v.x - mu) * rs * g.x + be.x,
                                    (v.y - mu) * rs * g.y + be.y);
    __half2 h23 = __floats2half2_rn((v.z - mu) * rs * g.z + be.z,
                                    (v.w - mu) * rs * g.w + be.w);
    uint2 pk = make_uint2(h2_bits(h01), h2_bits(h23));
    *reinterpret_cast<uint2*>(out + (size_t)row * DIM + c) = pk;
}

// ---------------------------------------------------------------------------
// fp16 mma.sync GEMM: C[M,N] = epi(A[M,K] @ B[K,N] + bias)
//   CTA 64x128, BK=32, 8 warps (32x32 warp tiles), 3-stage cp.async,
//   fully unrolled K-loop, 4 CTAs/SM (32 warps).
//   EPI 0: GELU -> fp16   EPI 1: +resid -> fp32 via smem-staged coalesced RMW
// ---------------------------------------------------------------------------
static constexpr int AS_STRIDE = 40;    // halves per A smem row (64 rows): 80B
static constexpr int BS_STRIDE = 136;   // halves per B smem row (32 rows): 272B
static constexpr int A_HALVES  = 64 * AS_STRIDE;                     // 2560
static constexpr int STAGE_BYTES = (A_HALVES + 32 * BS_STRIDE) * 2;  // 13824
static constexpr int SMEM_BYTES  = 3 * STAGE_BYTES;                  // 41472
static constexpr int OUT_STRIDE = 132;  // fp32 staging stride (EPI 1)

template <int K, int N, int EPI>
__global__ void __launch_bounds__(256, 4)
mma_gemm(const __half* __restrict__ A, const __half* __restrict__ B,
         const float* __restrict__ bias, void* __restrict__ Cv,
         const float* __restrict__ resid) {
    constexpr int BM = 64, BN = 128, BK = 32;
    constexpr int NT = K / BK;
    extern __shared__ __half sm[];
    const uint32_t sb = smem_u32(sm);
    const int bm = blockIdx.y * BM;
    const int bn = blockIdx.x * BN;
    const int tid  = threadIdx.x;
    const int warp = tid >> 5, lane = tid & 31;
    const int wm = warp >> 2, wn = warp & 3;     // warp tile rows wm*32, cols wn*32

    float acc[2][4][4];
    #pragma unroll
    for (int mt = 0; mt < 2; mt++)
        #pragma unroll
        for (int nt = 0; nt < 4; nt++)
            #pragma unroll
            for (int r = 0; r < 4; r++) acc[mt][nt][r] = 0.0f;

    // per-thread gmem bases for cp.async
    const int a_r = tid >> 2, a_c = tid & 3;         // A: 64 rows x 4 chunks = 256
    const int b_r = tid >> 4, b_c = tid & 15;        // B: 32(x2) rows x 16 chunks
    const __half* a_src0 = A + (size_t)(bm + a_r) * K + a_c * 8;
    const __half* b_src0 = B + (size_t)b_r * N + bn + b_c * 8;
    const uint32_t a_dst_off = (uint32_t)(a_r * AS_STRIDE + a_c * 8) * 2;
    const uint32_t b_dst_off = (uint32_t)(A_HALVES + b_r * BS_STRIDE + b_c * 8) * 2;

    auto load_tile = [&](int s, int t) {
        const uint32_t base = sb + (uint32_t)(s * STAGE_BYTES);
        cp16(base + a_dst_off, a_src0 + (size_t)t * BK);
        cp16(base + b_dst_off, b_src0 + (size_t)t * BK * N);
        cp16(base + b_dst_off + 16 * BS_STRIDE * 2, b_src0 + (size_t)(t * BK + 16) * N);
        cp_commit();
    };

    // hoisted ldmatrix fragment offsets (within a stage)
    const uint32_t a_frag_off = (uint32_t)((wm * 32 + (lane & 15)) * AS_STRIDE
                                           + 8 * (lane >> 4)) * 2;
    const uint32_t b_frag_off = (uint32_t)(A_HALVES * 2)
        + (uint32_t)((lane & 15) * BS_STRIDE + wn * 32 + 8 * (lane >> 4)) * 2;

    load_tile(0, 0);
    if (NT > 1) load_tile(1, 1);

    #pragma unroll
    for (int t = 0; t < NT; t++) {
        if (t + 1 < NT) cp_wait<1>(); else cp_wait<0>();
        __syncthreads();
        if (t + 2 < NT) load_tile((t + 2) % 3, t + 2);

        const uint32_t stage = sb + (uint32_t)((t % 3) * STAGE_BYTES);
        #pragma unroll
        for (int kk = 0; kk < 2; kk++) {
            uint32_t a[2][4], b[2][4];
            #pragma unroll
            for (int mt = 0; mt < 2; mt++)
                ldsm_x4(a[mt], stage + a_frag_off
                        + (uint32_t)(mt * 16 * AS_STRIDE + kk * 16) * 2);
            #pragma unroll
            for (int np = 0; np < 2; np++)
                ldsm_x4_t(b[np], stage + b_frag_off
                          + (uint32_t)(np * 16 + kk * 16 * BS_STRIDE) * 2);
            #pragma unroll
            for (int mt = 0; mt < 2; mt++)
                #pragma unroll
                for (int nt = 0; nt < 4; nt++)
                    mma_f16(acc[mt][nt], a[mt], &b[nt >> 1][(nt & 1) * 2]);
        }
    }

    // ---- epilogue ----
    const int g = lane >> 2, tg = lane & 3;
    if (EPI == 0) {
        #pragma unroll
        for (int mt = 0; mt < 2; mt++) {
            #pragma unroll
            for (int nt = 0; nt < 4; nt++) {
                const int col = bn + wn * 32 + nt * 8 + tg * 2;
                const float bx = __ldg(bias + col), by = __ldg(bias + col + 1);
                #pragma unroll
                for (int h = 0; h < 2; h++) {
                    const int row = bm + wm * 32 + mt * 16 + g + h * 8;
                    float ox = acc[mt][nt][2 * h + 0] + bx;
                    float oy = acc[mt][nt][2 * h + 1] + by;
                    __half2 hv = __floats2half2_rn(gelu_f(ox), gelu_f(oy));
                    *reinterpret_cast<__half2*>((__half*)Cv + (size_t)row * N + col) = hv;
                }
            }
        }
    } else {
        // stage the 64x128 fp32 tile in smem, then coalesced float4 RMW
        __syncthreads();                       // all mainloop smem reads done
        float* stg = reinterpret_cast<float*>(sm);
        #pragma unroll
        for (int mt = 0; mt < 2; mt++) {
            #pragma unroll
            for (int nt = 0; nt < 4; nt++) {
                const int col = wn * 32 + nt * 8 + tg * 2;
                const float bx = __ldg(bias + bn + col), by = __ldg(bias + bn + col + 1);
                #pragma unroll
                for (int h = 0; h < 2; h++) {
                    const int row = wm * 32 + mt * 16 + g + h * 8;
                    float2 o;
                    o.x = acc[mt][nt][2 * h + 0] + bx;
                    o.y = acc[mt][nt][2 * h + 1] + by;
                    *reinterpret_cast<float2*>(&stg[row * OUT_STRIDE + col]) = o;
                }
            }
        }
        __syncthreads();
        #pragma unroll
        for (int j = 0; j < 8; j++) {
            const int idx = tid + j * 256;          // 0..2047
            const int r = idx >> 5, c4 = (idx & 31) * 4;
            float4 v = *reinterpret_cast<const float4*>(&stg[r * OUT_STRIDE + c4]);
            const size_t go = (size_t)(bm + r) * N + bn + c4;
            const float4 rr = *reinterpret_cast<const float4*>(resid + go);
            v.x += rr.x; v.y += rr.y; v.z += rr.z; v.w += rr.w;
            *reinterpret_cast<float4*>((float*)Cv + go) = v;
        }
    }
}

// ---------------------------------------------------------------------------
extern "C" void kernel_launch(void* const* d_in, const int* in_sizes, int n_in,
                              void* d_out, int out_size) {
    const float* x     = (const float*)d_in[0];
    const float* gamma = (const float*)d_in[1];
    const float* beta  = (const float*)d_in[2];
    const float* W1    = (const float*)d_in[3];
    const float* b1    = (const float*)d_in[4];
    const float* W2    = (const float*)d_in[5];
    const float* b2    = (const float*)d_in[6];
    const float* W3    = (const float*)d_in[7];
    const float* b3    = (const float*)d_in[8];
    const float* W4    = (const float*)d_in[9];
    const float* b4    = (const float*)d_in[10];
    float* out = (float*)d_out;

    __half *ln, *buf1, *buf2, *w1, *w2, *w3, *w4;
    cudaGetSymbolAddress((void**)&ln,   g_lnh);
    cudaGetSymbolAddress((void**)&buf1, g_buf1);
    cudaGetSymbolAddress((void**)&buf2, g_buf2);
    cudaGetSymbolAddress((void**)&w1,   g_w1h);
    cudaGetSymbolAddress((void**)&w2,   g_w2h);
    cudaGetSymbolAddress((void**)&w3,   g_w3h);
    cudaGetSymbolAddress((void**)&w4,   g_w4h);

    cudaFuncSetAttribute(mma_gemm<DIM,  HMID, 0>, cudaFuncAttributeMaxDynamicSharedMemorySize, SMEM_BYTES);
    cudaFuncSetAttribute(mma_gemm<HMID, HMID, 0>, cudaFuncAttributeMaxDynamicSharedMemorySize, SMEM_BYTES);
    cudaFuncSetAttribute(mma_gemm<HMID, HLOW, 0>, cudaFuncAttributeMaxDynamicSharedMemorySize, SMEM_BYTES);
    cudaFuncSetAttribute(mma_gemm<HLOW, DIM,  1>, cudaFuncAttributeMaxDynamicSharedMemorySize, SMEM_BYTES);

    prep_kernel<<<ROWS + WBLOCKS, 256>>>(x, gamma, beta, ln, W1, W2, W3, W4);

    // GEMM1: LN(x)[32768,1024] @ W1 -> gelu -> buf1 (fp16)
    mma_gemm<DIM, HMID, 0>
        <<<dim3(HMID / 128, ROWS / 64), 256, SMEM_BYTES>>>(ln, w1, b1, buf1, nullptr);
    // GEMM2: buf1 @ W2 -> gelu -> buf2 (fp16)
    mma_gemm<HMID, HMID, 0>
        <<<dim3(HMID / 128, ROWS / 64), 256, SMEM_BYTES>>>(buf1, w2, b2, buf2, nullptr);
    // GEMM3: buf2 @ W3 -> gelu -> buf1 (fp16)
    mma_gemm<HMID, HLOW, 0>
        <<<dim3(HLOW / 128, ROWS / 64), 256, SMEM_BYTES>>>(buf2, w3, b3, buf1, nullptr);
    // GEMM4: buf1 @ W4 + b4 + x -> out (fp32)
    mma_gemm<HLOW, DIM, 1>
        <<<dim3(DIM / 128, ROWS / 64), 256, SMEM_BYTES>>>(buf1, w4, b4, out, x);
}